// round 8
// baseline (speedup 1.0000x reference)
#include <cuda_runtime.h>
#include <math.h>

#define RR       2336
#define CIN      4
#define COUT     16
#define NK       2
#define NTHREADS 768
#define NWARP    24
#define RPTF     3            // full j iterations (3*768 = 2304)
#define RPT      4
#define TAILN    32           // 2336 - 2304 (warp 0 only -> warp-uniform)
#define RPAD     20           // floats per smem row (conflict-free float4 slots)

// W repacked: [k][og][i][r] float4 (float4 covers outputs o = og*4 .. og*4+3)
__device__ float4 g_Wt4[NK * 16 * RR];

__global__ void wtrans_kernel(const float* __restrict__ W) {
    int t = blockIdx.x * blockDim.x + threadIdx.x;
    if (t >= NK * 16 * RR) return;
    int r  = t % RR;
    int q  = t / RR;          // k*16 + og*4 + i
    int i  = q & 3;
    int og = (q >> 2) & 3;
    int k  = q >> 4;
    const float4* src = (const float4*)W;   // [(k,r,i)][og]
    g_Wt4[t] = src[((k * RR + r) * CIN + i) * 4 + og];
}

// two-stage block reduction: intra-warp shfl, then warp 0 combines (N <= 32)
template <int N>
__device__ __forceinline__ void block_sum(float* v, float* red, int lane, int wid) {
#pragma unroll
    for (int n = 0; n < N; ++n) {
        float x = v[n];
#pragma unroll
        for (int off = 16; off > 0; off >>= 1)
            x += __shfl_xor_sync(0xffffffffu, x, off);
        v[n] = x;
    }
    __syncthreads();          // previous users of red are done
    if (lane == 0) {
#pragma unroll
        for (int n = 0; n < N; ++n) red[wid * N + n] = v[n];
    }
    __syncthreads();
    if (wid == 0 && lane < N) {
        float t = red[lane];
#pragma unroll
        for (int w = 1; w < NWARP; ++w) t += red[w * N + lane];
        red[lane] = t;        // each lane owns its column; safe overwrite
    }
    __syncthreads();
#pragma unroll
    for (int n = 0; n < N; ++n) v[n] = red[n];   // broadcast reads
}

__device__ __forceinline__ void squash16(const float* s, float* v) {
    float n0 = 0.f, n1 = 0.f;
#pragma unroll
    for (int o = 0; o < 8; ++o) {
        n0 = fmaf(s[o], s[o], n0);
        n1 = fmaf(s[o + 8], s[o + 8], n1);
    }
    float n = n0 + n1;
    float f = sqrtf(n) / (1.f + n);
#pragma unroll
    for (int o = 0; o < COUT; ++o) v[o] = s[o] * f;
}

__device__ __forceinline__ float dot16(const float* a, const float* b) {
    float d0 = 0.f, d1 = 0.f, d2 = 0.f, d3 = 0.f;
#pragma unroll
    for (int o = 0; o < 4; ++o) {
        d0 = fmaf(a[o],      b[o],      d0);
        d1 = fmaf(a[o + 4],  b[o + 4],  d1);
        d2 = fmaf(a[o + 8],  b[o + 8],  d2);
        d3 = fmaf(a[o + 12], b[o + 12], d3);
    }
    return (d0 + d1) + (d2 + d3);
}

// one block = one batch; u_ji lives entirely in smem (thread-private rows)
__global__ __launch_bounds__(NTHREADS, 1)
void caps_kernel(const float* __restrict__ u, float* __restrict__ out) {
    extern __shared__ float sm[];
    float4* uji4 = (float4*)sm;         // route r, group og at slot r*5+og
    float*  red  = sm + RR * RPAD;

    const int tid  = threadIdx.x;
    const int lane = tid & 31;
    const int wid  = tid >> 5;
    const int b    = blockIdx.x;
    const float4* up = (const float4*)(u + (size_t)b * RR * CIN);
    const bool tailok = (tid < TAILN);  // warp-uniform (warp 0 only)

    float cls[NK];

    for (int k = 0; k < NK; ++k) {
        const float4* Wt4 = g_Wt4 + k * 16 * RR;

        // ===== Phase A: u_ji -> smem, init route-sum folded into same pass =====
        float ss[COUT];
#pragma unroll
        for (int o = 0; o < COUT; ++o) ss[o] = 0.f;

#define ROUTE_A(RVAL)                                                          \
        {                                                                      \
            const int r_ = (RVAL);                                             \
            float4 a = up[r_];                                                 \
            _Pragma("unroll")                                                  \
            for (int og = 0; og < 4; ++og) {                                   \
                float4 w0 = Wt4[(og * 4 + 0) * RR + r_];                       \
                float4 w1 = Wt4[(og * 4 + 1) * RR + r_];                       \
                float4 w2 = Wt4[(og * 4 + 2) * RR + r_];                       \
                float4 w3 = Wt4[(og * 4 + 3) * RR + r_];                       \
                float e0 = fmaf(a.x,w0.x, fmaf(a.y,w1.x, fmaf(a.z,w2.x, a.w*w3.x))); \
                float e1 = fmaf(a.x,w0.y, fmaf(a.y,w1.y, fmaf(a.z,w2.y, a.w*w3.y))); \
                float e2 = fmaf(a.x,w0.z, fmaf(a.y,w1.z, fmaf(a.z,w2.z, a.w*w3.z))); \
                float e3 = fmaf(a.x,w0.w, fmaf(a.y,w1.w, fmaf(a.z,w2.w, a.w*w3.w))); \
                uji4[r_ * 5 + og] = make_float4(e0, e1, e2, e3);               \
                ss[og * 4 + 0] += e0; ss[og * 4 + 1] += e1;                    \
                ss[og * 4 + 2] += e2; ss[og * 4 + 3] += e3;                    \
            }                                                                  \
        }

#pragma unroll
        for (int j = 0; j < RPTF; ++j)
            ROUTE_A(tid + j * NTHREADS)
        if (tailok)
            ROUTE_A(tid + RPTF * NTHREADS)

        // ===== init reduction + squash =====
        float v[COUT];
        block_sum<COUT>(ss, red, lane, wid);
#pragma unroll
        for (int o = 0; o < COUT; ++o) ss[o] *= (1.f / RR);
        squash16(ss, v);

        // ===== 2 fused routing iterations (single sweep each) =====
        float blr[RPT];
#pragma unroll
        for (int it = 0; it < 2; ++it) {
            float acc[COUT + 1];
#pragma unroll
            for (int o = 0; o <= COUT; ++o) acc[o] = 0.f;

#define SWEEP(JIDX, RVAL)                                                      \
            {                                                                  \
                const int r_ = (RVAL);                                         \
                float4 q0 = uji4[r_ * 5 + 0];                                  \
                float4 q1 = uji4[r_ * 5 + 1];                                  \
                float4 q2 = uji4[r_ * 5 + 2];                                  \
                float4 q3 = uji4[r_ * 5 + 3];                                  \
                float qq[COUT] = {q0.x,q0.y,q0.z,q0.w, q1.x,q1.y,q1.z,q1.w,    \
                                  q2.x,q2.y,q2.z,q2.w, q3.x,q3.y,q3.z,q3.w};   \
                float d  = dot16(qq, v);                                       \
                float nb = (it == 0) ? d : (blr[JIDX] + d);                    \
                blr[JIDX] = nb;                                                \
                float w = __expf(nb);                                          \
                acc[COUT] += w;                                                \
                _Pragma("unroll")                                              \
                for (int o = 0; o < COUT; ++o)                                 \
                    acc[o] = fmaf(w, qq[o], acc[o]);                           \
            }

#pragma unroll
            for (int j = 0; j < RPTF; ++j)
                SWEEP(j, tid + j * NTHREADS)
            if (tailok)
                SWEEP(RPTF, tid + RPTF * NTHREADS)

            block_sum<COUT + 1>(acc, red, lane, wid);
            float invZ = 1.f / acc[COUT];
            float s[COUT];
#pragma unroll
            for (int o = 0; o < COUT; ++o) s[o] = acc[o] * invZ;
            squash16(s, v);
        }
        cls[k] = sqrtf(dot16(v, v));
        // uji4 rows are thread-private; block_sum barriers order the k loop
    }

    // ===== final 2-way softmax =====
    if (tid == 0) {
        float m = fmaxf(cls[0], cls[1]);
        float e0 = __expf(cls[0] - m), e1 = __expf(cls[1] - m);
        float inv = 1.f / (e0 + e1);
        out[b * NK + 0] = e0 * inv;
        out[b * NK + 1] = e1 * inv;
    }
}

extern "C" void kernel_launch(void* const* d_in, const int* in_sizes, int n_in,
                              void* d_out, int out_size) {
    const float* u = (const float*)d_in[0];   // [1024, 2336, 4]
    const float* W = (const float*)d_in[1];   // [2, 2336, 4, 16]
    float* out = (float*)d_out;               // [1024, 2]

    const int wtotal = NK * 16 * RR;
    wtrans_kernel<<<(wtotal + 255) / 256, 256>>>(W);

    const int smem_bytes = (RR * RPAD + NWARP * 17 + 16) * sizeof(float);
    cudaFuncSetAttribute(caps_kernel,
                         cudaFuncAttributeMaxDynamicSharedMemorySize, smem_bytes);
    caps_kernel<<<1024, NTHREADS, smem_bytes>>>(u, out);
}

// round 9
// speedup vs baseline: 1.4468x; 1.4468x over previous
#include <cuda_runtime.h>
#include <cuda_fp16.h>
#include <math.h>

#define RR       2336
#define CIN      4
#define COUT     16
#define NK       2
#define NTHREADS 512
#define NWARP    16
#define RPTF     4            // full j iterations (4*512 = 2048)
#define RPT      5
#define TAILN    288          // 2336 - 2048 (9 full warps -> warp-uniform tail)

#define H2(x) (*(half2*)&(x))

// W as half: uint4 = 8 halves. Layout [k][i][h][r], h selects outputs h*8..h*8+7
__device__ uint4 g_Wh[NK * CIN * 2 * RR];

__global__ void wtrans_kernel(const float* __restrict__ W) {
    int t = blockIdx.x * blockDim.x + threadIdx.x;
    if (t >= NK * CIN * 2 * RR) return;
    int r = t % RR;
    int q = t / RR;           // k*8 + i*2 + h
    int h = q & 1;
    int i = (q >> 1) & 3;
    int k = q >> 3;
    const float* s = W + (((size_t)(k * RR + r) * CIN + i) * COUT + h * 8);
    uint4 d;
    H2(d.x) = __floats2half2_rn(s[0], s[1]);
    H2(d.y) = __floats2half2_rn(s[2], s[3]);
    H2(d.z) = __floats2half2_rn(s[4], s[5]);
    H2(d.w) = __floats2half2_rn(s[6], s[7]);
    g_Wh[t] = d;
}

// two-stage block reduction: intra-warp shfl, then warp 0 combines (N <= 32)
template <int N>
__device__ __forceinline__ void block_sum(float* v, float* red, int lane, int wid) {
#pragma unroll
    for (int n = 0; n < N; ++n) {
        float x = v[n];
#pragma unroll
        for (int off = 16; off > 0; off >>= 1)
            x += __shfl_xor_sync(0xffffffffu, x, off);
        v[n] = x;
    }
    __syncthreads();
    if (lane == 0) {
#pragma unroll
        for (int n = 0; n < N; ++n) red[wid * N + n] = v[n];
    }
    __syncthreads();
    if (wid == 0 && lane < N) {
        float t = red[lane];
#pragma unroll
        for (int w = 1; w < NWARP; ++w) t += red[w * N + lane];
        red[lane] = t;
    }
    __syncthreads();
#pragma unroll
    for (int n = 0; n < N; ++n) v[n] = red[n];
}

__device__ __forceinline__ void squash16(const float* s, float* v) {
    float n0 = 0.f, n1 = 0.f;
#pragma unroll
    for (int o = 0; o < 8; ++o) {
        n0 = fmaf(s[o], s[o], n0);
        n1 = fmaf(s[o + 8], s[o + 8], n1);
    }
    float n = n0 + n1;
    float f = sqrtf(n) / (1.f + n);
#pragma unroll
    for (int o = 0; o < COUT; ++o) v[o] = s[o] * f;
}

__device__ __forceinline__ float dot16(const float* a, const float* b) {
    float d0 = 0.f, d1 = 0.f, d2 = 0.f, d3 = 0.f;
#pragma unroll
    for (int o = 0; o < 4; ++o) {
        d0 = fmaf(a[o],      b[o],      d0);
        d1 = fmaf(a[o + 4],  b[o + 4],  d1);
        d2 = fmaf(a[o + 8],  b[o + 8],  d2);
        d3 = fmaf(a[o + 12], b[o + 12], d3);
    }
    return (d0 + d1) + (d2 + d3);
}

// one block = one batch; u_ji in smem as half2 (two lane-consecutive uint4 arrays)
__global__ __launch_bounds__(NTHREADS, 1)
void caps_kernel(const float* __restrict__ u, float* __restrict__ out) {
    extern __shared__ float sm[];
    uint4* ujiA = (uint4*)sm;               // outputs 0..7 of route r
    uint4* ujiB = ujiA + RR;                // outputs 8..15
    float* red  = (float*)(ujiB + RR);

    const int tid  = threadIdx.x;
    const int lane = tid & 31;
    const int wid  = tid >> 5;
    const int b    = blockIdx.x;
    const float4* up = (const float4*)(u + (size_t)b * RR * CIN);
    const bool tailok = (tid < TAILN);      // warp-uniform

    float cls[NK];

    for (int k = 0; k < NK; ++k) {
        const uint4* WhK = g_Wh + k * (CIN * 2 * RR);

        // ===== Phase A: u_ji (half2 math) -> smem; init route-sum in half2 =====
        half2 ssh[8];
#pragma unroll
        for (int p = 0; p < 8; ++p) ssh[p] = __floats2half2_rn(0.f, 0.f);

#define ROUTE_A(RVAL)                                                          \
        {                                                                      \
            const int r_ = (RVAL);                                             \
            float4 a = up[r_];                                                 \
            half2 ah[4] = {__float2half2_rn(a.x), __float2half2_rn(a.y),       \
                           __float2half2_rn(a.z), __float2half2_rn(a.w)};      \
            half2 ac[8];                                                       \
            _Pragma("unroll")                                                  \
            for (int p = 0; p < 8; ++p) ac[p] = __floats2half2_rn(0.f, 0.f);   \
            _Pragma("unroll")                                                  \
            for (int i = 0; i < 4; ++i) {                                      \
                uint4 w0 = WhK[(i * 2 + 0) * RR + r_];                         \
                uint4 w1 = WhK[(i * 2 + 1) * RR + r_];                         \
                ac[0] = __hfma2(ah[i], H2(w0.x), ac[0]);                       \
                ac[1] = __hfma2(ah[i], H2(w0.y), ac[1]);                       \
                ac[2] = __hfma2(ah[i], H2(w0.z), ac[2]);                       \
                ac[3] = __hfma2(ah[i], H2(w0.w), ac[3]);                       \
                ac[4] = __hfma2(ah[i], H2(w1.x), ac[4]);                       \
                ac[5] = __hfma2(ah[i], H2(w1.y), ac[5]);                       \
                ac[6] = __hfma2(ah[i], H2(w1.z), ac[6]);                       \
                ac[7] = __hfma2(ah[i], H2(w1.w), ac[7]);                       \
            }                                                                  \
            uint4 sa, sb;                                                      \
            H2(sa.x) = ac[0]; H2(sa.y) = ac[1]; H2(sa.z) = ac[2]; H2(sa.w) = ac[3]; \
            H2(sb.x) = ac[4]; H2(sb.y) = ac[5]; H2(sb.z) = ac[6]; H2(sb.w) = ac[7]; \
            ujiA[r_] = sa; ujiB[r_] = sb;                                      \
            _Pragma("unroll")                                                  \
            for (int p = 0; p < 8; ++p) ssh[p] = __hadd2(ssh[p], ac[p]);       \
        }

#pragma unroll
        for (int j = 0; j < RPTF; ++j)
            ROUTE_A(tid + j * NTHREADS)
        if (tailok)
            ROUTE_A(tid + RPTF * NTHREADS)

        // ===== init reduction + squash (fp32) =====
        float ss[COUT], v[COUT];
#pragma unroll
        for (int p = 0; p < 8; ++p) {
            float2 f = __half22float2(ssh[p]);
            ss[2 * p] = f.x; ss[2 * p + 1] = f.y;
        }
        block_sum<COUT>(ss, red, lane, wid);
#pragma unroll
        for (int o = 0; o < COUT; ++o) ss[o] *= (1.f / RR);
        squash16(ss, v);

        // ===== 2 fused routing iterations (single sweep each, fp32 math) =====
        float blr[RPT];
#pragma unroll
        for (int it = 0; it < 2; ++it) {
            float acc[COUT + 1];
#pragma unroll
            for (int o = 0; o <= COUT; ++o) acc[o] = 0.f;

#define SWEEP(JIDX, RVAL)                                                      \
            {                                                                  \
                const int r_ = (RVAL);                                         \
                uint4 qa = ujiA[r_];                                           \
                uint4 qb = ujiB[r_];                                           \
                float qq[COUT];                                                \
                float2 f;                                                      \
                f = __half22float2(H2(qa.x)); qq[0] = f.x;  qq[1] = f.y;       \
                f = __half22float2(H2(qa.y)); qq[2] = f.x;  qq[3] = f.y;       \
                f = __half22float2(H2(qa.z)); qq[4] = f.x;  qq[5] = f.y;       \
                f = __half22float2(H2(qa.w)); qq[6] = f.x;  qq[7] = f.y;       \
                f = __half22float2(H2(qb.x)); qq[8] = f.x;  qq[9] = f.y;       \
                f = __half22float2(H2(qb.y)); qq[10] = f.x; qq[11] = f.y;      \
                f = __half22float2(H2(qb.z)); qq[12] = f.x; qq[13] = f.y;      \
                f = __half22float2(H2(qb.w)); qq[14] = f.x; qq[15] = f.y;      \
                float d  = dot16(qq, v);                                       \
                float nb = (it == 0) ? d : (blr[JIDX] + d);                    \
                blr[JIDX] = nb;                                                \
                float w = __expf(nb);                                          \
                acc[COUT] += w;                                                \
                _Pragma("unroll")                                              \
                for (int o = 0; o < COUT; ++o)                                 \
                    acc[o] = fmaf(w, qq[o], acc[o]);                           \
            }

#pragma unroll
            for (int j = 0; j < RPTF; ++j)
                SWEEP(j, tid + j * NTHREADS)
            if (tailok)
                SWEEP(RPT - 1, tid + RPTF * NTHREADS)

            block_sum<COUT + 1>(acc, red, lane, wid);
            float invZ = 1.f / acc[COUT];
            float s[COUT];
#pragma unroll
            for (int o = 0; o < COUT; ++o) s[o] = acc[o] * invZ;
            squash16(s, v);
        }
        cls[k] = sqrtf(dot16(v, v));
        // smem rows are thread-private; block_sum barriers order the k loop
    }

    // ===== final 2-way softmax =====
    if (tid == 0) {
        float m = fmaxf(cls[0], cls[1]);
        float e0 = __expf(cls[0] - m), e1 = __expf(cls[1] - m);
        float inv = 1.f / (e0 + e1);
        out[b * NK + 0] = e0 * inv;
        out[b * NK + 1] = e1 * inv;
    }
}

extern "C" void kernel_launch(void* const* d_in, const int* in_sizes, int n_in,
                              void* d_out, int out_size) {
    const float* u = (const float*)d_in[0];   // [1024, 2336, 4]
    const float* W = (const float*)d_in[1];   // [2, 2336, 4, 16]
    float* out = (float*)d_out;               // [1024, 2]

    const int wtotal = NK * CIN * 2 * RR;
    wtrans_kernel<<<(wtotal + 255) / 256, 256>>>(W);

    const int smem_bytes = 2 * RR * sizeof(uint4) + (NWARP * 17 + 16) * sizeof(float);
    cudaFuncSetAttribute(caps_kernel,
                         cudaFuncAttributeMaxDynamicSharedMemorySize, smem_bytes);
    caps_kernel<<<1024, NTHREADS, smem_bytes>>>(u, out);
}

// round 11
// speedup vs baseline: 1.5402x; 1.0645x over previous
#include <cuda_runtime.h>
#include <cuda_fp16.h>
#include <math.h>

#define RR       2336
#define CIN      4
#define COUT     16
#define NK       2
#define NTHREADS 512
#define NWARP    16
#define RPTF     4            // full j iterations (4*512 = 2048)
#define RPT      5
#define TAILN    288          // 2336 - 2048 (9 full warps -> warp-uniform tail)
#define REDSZ    (NWARP * 34 + 40)

#define H2(x) (*(half2*)&(x))

// W as half: uint4 = 8 halves. Layout [k][i][h][r], h selects outputs h*8..h*8+7
__device__ uint4 g_Wh[NK * CIN * 2 * RR];

__global__ void wtrans_kernel(const float* __restrict__ W) {
    int t = blockIdx.x * blockDim.x + threadIdx.x;
    if (t >= NK * CIN * 2 * RR) return;
    int r = t % RR;
    int q = t / RR;           // k*8 + i*2 + h
    int h = q & 1;
    int i = (q >> 1) & 3;
    int k = q >> 3;
    const float* s = W + (((size_t)(k * RR + r) * CIN + i) * COUT + h * 8);
    uint4 d;
    H2(d.x) = __floats2half2_rn(s[0], s[1]);
    H2(d.y) = __floats2half2_rn(s[2], s[3]);
    H2(d.z) = __floats2half2_rn(s[4], s[5]);
    H2(d.w) = __floats2half2_rn(s[6], s[7]);
    g_Wh[t] = d;
}

// 2-sync block reduction (ping-pong buffers make the guard sync unnecessary)
template <int N>
__device__ __forceinline__ void block_sum(float* v, float* red, int tid, int lane, int wid) {
#pragma unroll
    for (int n = 0; n < N; ++n) {
        float x = v[n];
#pragma unroll
        for (int off = 16; off > 0; off >>= 1)
            x += __shfl_xor_sync(0xffffffffu, x, off);
        v[n] = x;
    }
    if (lane == 0) {
#pragma unroll
        for (int n = 0; n < N; ++n) red[wid * N + n] = v[n];
    }
    __syncthreads();
    if (tid < N) {
        float t = red[tid];
#pragma unroll
        for (int w = 1; w < NWARP; ++w) t += red[w * N + tid];
        red[tid] = t;         // each combine lane owns its column
    }
    __syncthreads();
#pragma unroll
    for (int n = 0; n < N; ++n) v[n] = red[n];
}

__device__ __forceinline__ void squash16(const float* s, float* v) {
    float n0 = 0.f, n1 = 0.f;
#pragma unroll
    for (int o = 0; o < 8; ++o) {
        n0 = fmaf(s[o], s[o], n0);
        n1 = fmaf(s[o + 8], s[o + 8], n1);
    }
    float n = n0 + n1;
    float f = sqrtf(n) / (1.f + n);
#pragma unroll
    for (int o = 0; o < COUT; ++o) v[o] = s[o] * f;
}

__device__ __forceinline__ float dot16(const float* a, const float* b) {
    float d0 = 0.f, d1 = 0.f, d2 = 0.f, d3 = 0.f;
#pragma unroll
    for (int o = 0; o < 4; ++o) {
        d0 = fmaf(a[o],      b[o],      d0);
        d1 = fmaf(a[o + 4],  b[o + 4],  d1);
        d2 = fmaf(a[o + 8],  b[o + 8],  d2);
        d3 = fmaf(a[o + 12], b[o + 12], d3);
    }
    return (d0 + d1) + (d2 + d3);
}

#define UNPACK16(qa, qb, qq)                                                   \
    {                                                                          \
        float2 f;                                                              \
        f = __half22float2(H2(qa.x)); qq[0] = f.x;  qq[1] = f.y;               \
        f = __half22float2(H2(qa.y)); qq[2] = f.x;  qq[3] = f.y;               \
        f = __half22float2(H2(qa.z)); qq[4] = f.x;  qq[5] = f.y;               \
        f = __half22float2(H2(qa.w)); qq[6] = f.x;  qq[7] = f.y;               \
        f = __half22float2(H2(qb.x)); qq[8] = f.x;  qq[9] = f.y;               \
        f = __half22float2(H2(qb.y)); qq[10] = f.x; qq[11] = f.y;              \
        f = __half22float2(H2(qb.z)); qq[12] = f.x; qq[13] = f.y;              \
        f = __half22float2(H2(qb.w)); qq[14] = f.x; qq[15] = f.y;              \
    }

// one block = one batch; both k tiles in smem as half2
__global__ __launch_bounds__(NTHREADS, 1)
void caps_kernel(const float* __restrict__ u, float* __restrict__ out) {
    extern __shared__ float sm[];
    uint4* t0A = (uint4*)sm;          // k=0, outputs 0..7
    uint4* t0B = t0A + RR;            // k=0, outputs 8..15
    uint4* t1A = t0B + RR;            // k=1, outputs 0..7
    uint4* t1B = t1A + RR;            // k=1, outputs 8..15
    float* red0 = (float*)(t1B + RR); // ping-pong reduction buffers
    float* red1 = red0 + REDSZ;

    const int tid  = threadIdx.x;
    const int lane = tid & 31;
    const int wid  = tid >> 5;
    const int b    = blockIdx.x;
    const float4* up = (const float4*)(u + (size_t)b * RR * CIN);
    const bool tailok = (tid < TAILN);      // warp-uniform

    const uint4* W0 = g_Wh;
    const uint4* W1 = g_Wh + CIN * 2 * RR;

    // ===== Phase A: both k per u-load; init route-sums in half2 =====
    half2 ssh[16];
#pragma unroll
    for (int p = 0; p < 16; ++p) ssh[p] = __floats2half2_rn(0.f, 0.f);

#define ROUTE_A(RVAL)                                                          \
    {                                                                          \
        const int r_ = (RVAL);                                                 \
        float4 a = up[r_];                                                     \
        half2 ah[4] = {__float2half2_rn(a.x), __float2half2_rn(a.y),           \
                       __float2half2_rn(a.z), __float2half2_rn(a.w)};          \
        _Pragma("unroll")                                                      \
        for (int kk = 0; kk < 2; ++kk) {                                       \
            const uint4* Wk = kk ? W1 : W0;                                    \
            half2 ac[8];                                                       \
            _Pragma("unroll")                                                  \
            for (int p = 0; p < 8; ++p) ac[p] = __floats2half2_rn(0.f, 0.f);   \
            _Pragma("unroll")                                                  \
            for (int i = 0; i < 4; ++i) {                                      \
                uint4 w0 = Wk[(i * 2 + 0) * RR + r_];                          \
                uint4 w1 = Wk[(i * 2 + 1) * RR + r_];                          \
                ac[0] = __hfma2(ah[i], H2(w0.x), ac[0]);                       \
                ac[1] = __hfma2(ah[i], H2(w0.y), ac[1]);                       \
                ac[2] = __hfma2(ah[i], H2(w0.z), ac[2]);                       \
                ac[3] = __hfma2(ah[i], H2(w0.w), ac[3]);                       \
                ac[4] = __hfma2(ah[i], H2(w1.x), ac[4]);                       \
                ac[5] = __hfma2(ah[i], H2(w1.y), ac[5]);                       \
                ac[6] = __hfma2(ah[i], H2(w1.z), ac[6]);                       \
                ac[7] = __hfma2(ah[i], H2(w1.w), ac[7]);                       \
            }                                                                  \
            uint4 sa, sb;                                                      \
            H2(sa.x) = ac[0]; H2(sa.y) = ac[1]; H2(sa.z) = ac[2]; H2(sa.w) = ac[3]; \
            H2(sb.x) = ac[4]; H2(sb.y) = ac[5]; H2(sb.z) = ac[6]; H2(sb.w) = ac[7]; \
            if (kk) { t1A[r_] = sa; t1B[r_] = sb; }                            \
            else    { t0A[r_] = sa; t0B[r_] = sb; }                            \
            _Pragma("unroll")                                                  \
            for (int p = 0; p < 8; ++p)                                        \
                ssh[kk * 8 + p] = __hadd2(ssh[kk * 8 + p], ac[p]);             \
        }                                                                      \
    }

#pragma unroll
    for (int j = 0; j < RPTF; ++j)
        ROUTE_A(tid + j * NTHREADS)
    if (tailok)
        ROUTE_A(tid + RPTF * NTHREADS)

    // ===== merged init reduction + squash (fp32) =====
    float v0[COUT], v1[COUT];
    {
        float ss[32];
#pragma unroll
        for (int p = 0; p < 16; ++p) {
            float2 f = __half22float2(ssh[p]);
            ss[2 * p] = f.x; ss[2 * p + 1] = f.y;
        }
        block_sum<32>(ss, red0, tid, lane, wid);
#pragma unroll
        for (int o = 0; o < 32; ++o) ss[o] *= (1.f / RR);
        squash16(ss, v0);
        squash16(ss + 16, v1);
    }

    // ===== 2 fused routing iterations, both k per sweep =====
    float blr0[RPT], blr1[RPT];
#pragma unroll
    for (int it = 0; it < 2; ++it) {
        float av[34];
#pragma unroll
        for (int o = 0; o < 34; ++o) av[o] = 0.f;
        // av[0..15]=acc k0, av[16]=accw k0, av[17..32]=acc k1, av[33]=accw k1

#define SWEEP(JIDX, RVAL)                                                      \
        {                                                                      \
            const int r_ = (RVAL);                                             \
            uint4 qa0 = t0A[r_], qb0 = t0B[r_];                                \
            uint4 qa1 = t1A[r_], qb1 = t1B[r_];                                \
            float qq0[COUT], qq1[COUT];                                        \
            UNPACK16(qa0, qb0, qq0)                                            \
            UNPACK16(qa1, qb1, qq1)                                            \
            float d0 = dot16(qq0, v0);                                         \
            float d1 = dot16(qq1, v1);                                         \
            float nb0 = (it == 0) ? d0 : (blr0[JIDX] + d0);                    \
            float nb1 = (it == 0) ? d1 : (blr1[JIDX] + d1);                    \
            blr0[JIDX] = nb0; blr1[JIDX] = nb1;                                \
            float w0 = __expf(nb0);                                            \
            float w1 = __expf(nb1);                                            \
            av[16] += w0; av[33] += w1;                                        \
            _Pragma("unroll")                                                  \
            for (int o = 0; o < COUT; ++o) {                                   \
                av[o]      = fmaf(w0, qq0[o], av[o]);                          \
                av[17 + o] = fmaf(w1, qq1[o], av[17 + o]);                     \
            }                                                                  \
        }

#pragma unroll
        for (int j = 0; j < RPTF; ++j)
            SWEEP(j, tid + j * NTHREADS)
        if (tailok)
            SWEEP(RPT - 1, tid + RPTF * NTHREADS)

        block_sum<34>(av, (it == 0) ? red1 : red0, tid, lane, wid);

        float s[COUT];
        float iz0 = 1.f / av[16];
#pragma unroll
        for (int o = 0; o < COUT; ++o) s[o] = av[o] * iz0;
        squash16(s, v0);
        float iz1 = 1.f / av[33];
#pragma unroll
        for (int o = 0; o < COUT; ++o) s[o] = av[17 + o] * iz1;
        squash16(s, v1);
    }

    // ===== final 2-way softmax =====
    if (tid == 0) {
        float c0 = sqrtf(dot16(v0, v0));
        float c1 = sqrtf(dot16(v1, v1));
        float m = fmaxf(c0, c1);
        float e0 = __expf(c0 - m), e1 = __expf(c1 - m);
        float inv = 1.f / (e0 + e1);
        out[b * NK + 0] = e0 * inv;
        out[b * NK + 1] = e1 * inv;
    }
}

extern "C" void kernel_launch(void* const* d_in, const int* in_sizes, int n_in,
                              void* d_out, int out_size) {
    const float* u = (const float*)d_in[0];   // [1024, 2336, 4]
    const float* W = (const float*)d_in[1];   // [2, 2336, 4, 16]
    float* out = (float*)d_out;               // [1024, 2]

    const int wtotal = NK * CIN * 2 * RR;
    wtrans_kernel<<<(wtotal + 255) / 256, 256>>>(W);

    const int smem_bytes = 4 * RR * sizeof(uint4) + 2 * REDSZ * sizeof(float);
    cudaFuncSetAttribute(caps_kernel,
                         cudaFuncAttributeMaxDynamicSharedMemorySize, smem_bytes);
    caps_kernel<<<1024, NTHREADS, smem_bytes>>>(u, out);
}

// round 12
// speedup vs baseline: 1.6149x; 1.0485x over previous
#include <cuda_runtime.h>
#include <cuda_fp16.h>
#include <math.h>

#define RR       2336
#define CIN      4
#define COUT     16
#define NK       2
#define NTHREADS 512
#define NWARP    16
#define RPTF     4            // full j iterations (4*512 = 2048)
#define RPT      5
#define TAILN    288          // 2336 - 2048 (9 full warps -> warp-uniform tail)
#define REDSZ    (NWARP * 34 + 40)

#define H2(x) (*(half2*)&(x))

// W as half: uint4 = 8 halves. Layout [k][i][h][r], h selects outputs h*8..h*8+7
__device__ uint4 g_Wh[NK * CIN * 2 * RR];

__global__ void wtrans_kernel(const float* __restrict__ W) {
    int t = blockIdx.x * blockDim.x + threadIdx.x;
    if (t >= NK * CIN * 2 * RR) return;
    int r = t % RR;
    int q = t / RR;           // k*8 + i*2 + h
    int h = q & 1;
    int i = (q >> 1) & 3;
    int k = q >> 3;
    const float* s = W + (((size_t)(k * RR + r) * CIN + i) * COUT + h * 8);
    uint4 d;
    H2(d.x) = __floats2half2_rn(s[0], s[1]);
    H2(d.y) = __floats2half2_rn(s[2], s[3]);
    H2(d.z) = __floats2half2_rn(s[4], s[5]);
    H2(d.w) = __floats2half2_rn(s[6], s[7]);
    g_Wh[t] = d;
}

// 2-sync block reduction (ping-pong buffers make the guard sync unnecessary)
template <int N>
__device__ __forceinline__ void block_sum(float* v, float* red, int tid, int lane, int wid) {
#pragma unroll
    for (int n = 0; n < N; ++n) {
        float x = v[n];
#pragma unroll
        for (int off = 16; off > 0; off >>= 1)
            x += __shfl_xor_sync(0xffffffffu, x, off);
        v[n] = x;
    }
    if (lane == 0) {
#pragma unroll
        for (int n = 0; n < N; ++n) red[wid * N + n] = v[n];
    }
    __syncthreads();
    if (tid < N) {
        float t = red[tid];
#pragma unroll
        for (int w = 1; w < NWARP; ++w) t += red[w * N + tid];
        red[tid] = t;         // each combine lane owns its column
    }
    __syncthreads();
#pragma unroll
    for (int n = 0; n < N; ++n) v[n] = red[n];
}

__device__ __forceinline__ void squash16(const float* s, float* v) {
    float n0 = 0.f, n1 = 0.f;
#pragma unroll
    for (int o = 0; o < 8; ++o) {
        n0 = fmaf(s[o], s[o], n0);
        n1 = fmaf(s[o + 8], s[o + 8], n1);
    }
    float n = n0 + n1;
    float f = sqrtf(n) / (1.f + n);
#pragma unroll
    for (int o = 0; o < COUT; ++o) v[o] = s[o] * f;
}

__device__ __forceinline__ float dot16(const float* a, const float* b) {
    float d0 = 0.f, d1 = 0.f, d2 = 0.f, d3 = 0.f;
#pragma unroll
    for (int o = 0; o < 4; ++o) {
        d0 = fmaf(a[o],      b[o],      d0);
        d1 = fmaf(a[o + 4],  b[o + 4],  d1);
        d2 = fmaf(a[o + 8],  b[o + 8],  d2);
        d3 = fmaf(a[o + 12], b[o + 12], d3);
    }
    return (d0 + d1) + (d2 + d3);
}

// one block = one batch; both k tiles in smem as half2
__global__ __launch_bounds__(NTHREADS, 1)
void caps_kernel(const float* __restrict__ u, float* __restrict__ out) {
    extern __shared__ float sm[];
    uint4* t0A = (uint4*)sm;          // k=0, outputs 0..7
    uint4* t0B = t0A + RR;            // k=0, outputs 8..15
    uint4* t1A = t0B + RR;            // k=1, outputs 0..7
    uint4* t1B = t1A + RR;            // k=1, outputs 8..15
    float* red0 = (float*)(t1B + RR); // ping-pong reduction buffers
    float* red1 = red0 + REDSZ;

    const int tid  = threadIdx.x;
    const int lane = tid & 31;
    const int wid  = tid >> 5;
    const int b    = blockIdx.x;
    const float4* up = (const float4*)(u + (size_t)b * RR * CIN);
    const bool tailok = (tid < TAILN);      // warp-uniform

    const uint4* W0 = g_Wh;
    const uint4* W1 = g_Wh + CIN * 2 * RR;

    // ===== Phase A: both k per u-load; init route-sums in half2 =====
    half2 ssh[16];
#pragma unroll
    for (int p = 0; p < 16; ++p) ssh[p] = __floats2half2_rn(0.f, 0.f);

#define ROUTE_A(RVAL)                                                          \
    {                                                                          \
        const int r_ = (RVAL);                                                 \
        float4 a = up[r_];                                                     \
        half2 ah[4] = {__float2half2_rn(a.x), __float2half2_rn(a.y),           \
                       __float2half2_rn(a.z), __float2half2_rn(a.w)};          \
        _Pragma("unroll")                                                      \
        for (int kk = 0; kk < 2; ++kk) {                                       \
            const uint4* Wk = kk ? W1 : W0;                                    \
            half2 ac[8];                                                       \
            _Pragma("unroll")                                                  \
            for (int p = 0; p < 8; ++p) ac[p] = __floats2half2_rn(0.f, 0.f);   \
            _Pragma("unroll")                                                  \
            for (int i = 0; i < 4; ++i) {                                      \
                uint4 w0 = Wk[(i * 2 + 0) * RR + r_];                          \
                uint4 w1 = Wk[(i * 2 + 1) * RR + r_];                          \
                ac[0] = __hfma2(ah[i], H2(w0.x), ac[0]);                       \
                ac[1] = __hfma2(ah[i], H2(w0.y), ac[1]);                       \
                ac[2] = __hfma2(ah[i], H2(w0.z), ac[2]);                       \
                ac[3] = __hfma2(ah[i], H2(w0.w), ac[3]);                       \
                ac[4] = __hfma2(ah[i], H2(w1.x), ac[4]);                       \
                ac[5] = __hfma2(ah[i], H2(w1.y), ac[5]);                       \
                ac[6] = __hfma2(ah[i], H2(w1.z), ac[6]);                       \
                ac[7] = __hfma2(ah[i], H2(w1.w), ac[7]);                       \
            }                                                                  \
            uint4 sa, sb;                                                      \
            H2(sa.x) = ac[0]; H2(sa.y) = ac[1]; H2(sa.z) = ac[2]; H2(sa.w) = ac[3]; \
            H2(sb.x) = ac[4]; H2(sb.y) = ac[5]; H2(sb.z) = ac[6]; H2(sb.w) = ac[7]; \
            if (kk) { t1A[r_] = sa; t1B[r_] = sb; }                            \
            else    { t0A[r_] = sa; t0B[r_] = sb; }                            \
            _Pragma("unroll")                                                  \
            for (int p = 0; p < 8; ++p)                                        \
                ssh[kk * 8 + p] = __hadd2(ssh[kk * 8 + p], ac[p]);             \
        }                                                                      \
    }

#pragma unroll
    for (int j = 0; j < RPTF; ++j)
        ROUTE_A(tid + j * NTHREADS)
    if (tailok)
        ROUTE_A(tid + RPTF * NTHREADS)

    // ===== merged init reduction + squash (fp32) =====
    float v0[COUT], v1[COUT];
    {
        float ss[32];
#pragma unroll
        for (int p = 0; p < 16; ++p) {
            float2 f = __half22float2(ssh[p]);
            ss[2 * p] = f.x; ss[2 * p + 1] = f.y;
        }
        block_sum<32>(ss, red0, tid, lane, wid);
#pragma unroll
        for (int o = 0; o < 32; ++o) ss[o] *= (1.f / RR);
        squash16(ss, v0);
        squash16(ss + 16, v1);
    }

    // ===== 2 fused routing iterations, both k per sweep, half2 math =====
    float blr0[RPT], blr1[RPT];
#pragma unroll
    for (int it = 0; it < 2; ++it) {
        // pack v into half2
        half2 vh0[8], vh1[8];
#pragma unroll
        for (int p = 0; p < 8; ++p) {
            vh0[p] = __floats2half2_rn(v0[2 * p], v0[2 * p + 1]);
            vh1[p] = __floats2half2_rn(v1[2 * p], v1[2 * p + 1]);
        }
        half2 ach0[8], ach1[8];
#pragma unroll
        for (int p = 0; p < 8; ++p) {
            ach0[p] = __floats2half2_rn(0.f, 0.f);
            ach1[p] = __floats2half2_rn(0.f, 0.f);
        }
        float accw0 = 0.f, accw1 = 0.f;

#define SWEEP(JIDX, RVAL)                                                      \
        {                                                                      \
            const int r_ = (RVAL);                                             \
            uint4 qa0 = t0A[r_], qb0 = t0B[r_];                                \
            uint4 qa1 = t1A[r_], qb1 = t1B[r_];                                \
            half2 dp0 = __hmul2(H2(qa0.x), vh0[0]);                            \
            dp0 = __hfma2(H2(qa0.y), vh0[1], dp0);                             \
            dp0 = __hfma2(H2(qa0.z), vh0[2], dp0);                             \
            dp0 = __hfma2(H2(qa0.w), vh0[3], dp0);                             \
            dp0 = __hfma2(H2(qb0.x), vh0[4], dp0);                             \
            dp0 = __hfma2(H2(qb0.y), vh0[5], dp0);                             \
            dp0 = __hfma2(H2(qb0.z), vh0[6], dp0);                             \
            dp0 = __hfma2(H2(qb0.w), vh0[7], dp0);                             \
            half2 dp1 = __hmul2(H2(qa1.x), vh1[0]);                            \
            dp1 = __hfma2(H2(qa1.y), vh1[1], dp1);                             \
            dp1 = __hfma2(H2(qa1.z), vh1[2], dp1);                             \
            dp1 = __hfma2(H2(qa1.w), vh1[3], dp1);                             \
            dp1 = __hfma2(H2(qb1.x), vh1[4], dp1);                             \
            dp1 = __hfma2(H2(qb1.y), vh1[5], dp1);                             \
            dp1 = __hfma2(H2(qb1.z), vh1[6], dp1);                             \
            dp1 = __hfma2(H2(qb1.w), vh1[7], dp1);                             \
            float2 df0 = __half22float2(dp0);                                  \
            float2 df1 = __half22float2(dp1);                                  \
            float d0 = df0.x + df0.y;                                          \
            float d1 = df1.x + df1.y;                                          \
            float nb0 = (it == 0) ? d0 : (blr0[JIDX] + d0);                    \
            float nb1 = (it == 0) ? d1 : (blr1[JIDX] + d1);                    \
            blr0[JIDX] = nb0; blr1[JIDX] = nb1;                                \
            float w0 = __expf(nb0);                                            \
            float w1 = __expf(nb1);                                            \
            accw0 += w0; accw1 += w1;                                          \
            half2 wh0 = __float2half2_rn(w0);                                  \
            half2 wh1 = __float2half2_rn(w1);                                  \
            ach0[0] = __hfma2(wh0, H2(qa0.x), ach0[0]);                        \
            ach0[1] = __hfma2(wh0, H2(qa0.y), ach0[1]);                        \
            ach0[2] = __hfma2(wh0, H2(qa0.z), ach0[2]);                        \
            ach0[3] = __hfma2(wh0, H2(qa0.w), ach0[3]);                        \
            ach0[4] = __hfma2(wh0, H2(qb0.x), ach0[4]);                        \
            ach0[5] = __hfma2(wh0, H2(qb0.y), ach0[5]);                        \
            ach0[6] = __hfma2(wh0, H2(qb0.z), ach0[6]);                        \
            ach0[7] = __hfma2(wh0, H2(qb0.w), ach0[7]);                        \
            ach1[0] = __hfma2(wh1, H2(qa1.x), ach1[0]);                        \
            ach1[1] = __hfma2(wh1, H2(qa1.y), ach1[1]);                        \
            ach1[2] = __hfma2(wh1, H2(qa1.z), ach1[2]);                        \
            ach1[3] = __hfma2(wh1, H2(qa1.w), ach1[3]);                        \
            ach1[4] = __hfma2(wh1, H2(qb1.x), ach1[4]);                        \
            ach1[5] = __hfma2(wh1, H2(qb1.y), ach1[5]);                        \
            ach1[6] = __hfma2(wh1, H2(qb1.z), ach1[6]);                        \
            ach1[7] = __hfma2(wh1, H2(qb1.w), ach1[7]);                        \
        }

#pragma unroll
        for (int j = 0; j < RPTF; ++j)
            SWEEP(j, tid + j * NTHREADS)
        if (tailok)
            SWEEP(RPT - 1, tid + RPTF * NTHREADS)

        // convert per-thread half2 partials to fp32, reduce across block
        float av[34];
#pragma unroll
        for (int p = 0; p < 8; ++p) {
            float2 f0 = __half22float2(ach0[p]);
            float2 f1 = __half22float2(ach1[p]);
            av[2 * p]          = f0.x; av[2 * p + 1]      = f0.y;
            av[17 + 2 * p]     = f1.x; av[17 + 2 * p + 1] = f1.y;
        }
        av[16] = accw0; av[33] = accw1;

        block_sum<34>(av, (it == 0) ? red1 : red0, tid, lane, wid);

        float s[COUT];
        float iz0 = 1.f / av[16];
#pragma unroll
        for (int o = 0; o < COUT; ++o) s[o] = av[o] * iz0;
        squash16(s, v0);
        float iz1 = 1.f / av[33];
#pragma unroll
        for (int o = 0; o < COUT; ++o) s[o] = av[17 + o] * iz1;
        squash16(s, v1);
    }

    // ===== final 2-way softmax =====
    if (tid == 0) {
        float c0 = sqrtf(dot16(v0, v0));
        float c1 = sqrtf(dot16(v1, v1));
        float m = fmaxf(c0, c1);
        float e0 = __expf(c0 - m), e1 = __expf(c1 - m);
        float inv = 1.f / (e0 + e1);
        out[b * NK + 0] = e0 * inv;
        out[b * NK + 1] = e1 * inv;
    }
}

extern "C" void kernel_launch(void* const* d_in, const int* in_sizes, int n_in,
                              void* d_out, int out_size) {
    const float* u = (const float*)d_in[0];   // [1024, 2336, 4]
    const float* W = (const float*)d_in[1];   // [2, 2336, 4, 16]
    float* out = (float*)d_out;               // [1024, 2]

    const int wtotal = NK * CIN * 2 * RR;
    wtrans_kernel<<<(wtotal + 255) / 256, 256>>>(W);

    const int smem_bytes = 4 * RR * sizeof(uint4) + 2 * REDSZ * sizeof(float);
    cudaFuncSetAttribute(caps_kernel,
                         cudaFuncAttributeMaxDynamicSharedMemorySize, smem_bytes);
    caps_kernel<<<1024, NTHREADS, smem_bytes>>>(u, out);
}

// round 13
// speedup vs baseline: 1.7178x; 1.0637x over previous
#include <cuda_runtime.h>
#include <cuda_fp16.h>
#include <math.h>

#define RR       2336
#define CIN      4
#define COUT     16
#define NK       2
#define NTHREADS 512
#define NWARP    16
#define RPTF     4            // full j iterations (4*512 = 2048)
#define RPT      5
#define TAILN    288          // 2336 - 2048 (9 full warps -> warp-uniform tail)
#define NB       1024
#define REDSZ    (NWARP * 17 + 24)

#define H2(x) (*(half2*)&(x))

// W as half: uint4 = 8 halves. Layout [k][i][h][r], h selects outputs h*8..h*8+7
__device__ uint4 g_Wh[NK * CIN * 2 * RR];
// staged per-(b,k) class norms
__device__ float g_cls[NB * NK];

__global__ void wtrans_kernel(const float* __restrict__ W) {
    int t = blockIdx.x * blockDim.x + threadIdx.x;
    if (t >= NK * CIN * 2 * RR) return;
    int r = t % RR;
    int q = t / RR;           // k*8 + i*2 + h
    int h = q & 1;
    int i = (q >> 1) & 3;
    int k = q >> 3;
    const float* s = W + (((size_t)(k * RR + r) * CIN + i) * COUT + h * 8);
    uint4 d;
    H2(d.x) = __floats2half2_rn(s[0], s[1]);
    H2(d.y) = __floats2half2_rn(s[2], s[3]);
    H2(d.z) = __floats2half2_rn(s[4], s[5]);
    H2(d.w) = __floats2half2_rn(s[6], s[7]);
    g_Wh[t] = d;
}

// 2-sync block reduction (ping-pong buffers make the guard sync unnecessary)
template <int N>
__device__ __forceinline__ void block_sum(float* v, float* red, int tid, int lane, int wid) {
#pragma unroll
    for (int n = 0; n < N; ++n) {
        float x = v[n];
#pragma unroll
        for (int off = 16; off > 0; off >>= 1)
            x += __shfl_xor_sync(0xffffffffu, x, off);
        v[n] = x;
    }
    if (lane == 0) {
#pragma unroll
        for (int n = 0; n < N; ++n) red[wid * N + n] = v[n];
    }
    __syncthreads();
    if (tid < N) {
        float t = red[tid];
#pragma unroll
        for (int w = 1; w < NWARP; ++w) t += red[w * N + tid];
        red[tid] = t;         // each combine lane owns its column
    }
    __syncthreads();
#pragma unroll
    for (int n = 0; n < N; ++n) v[n] = red[n];
}

__device__ __forceinline__ void squash16(const float* s, float* v) {
    float n0 = 0.f, n1 = 0.f;
#pragma unroll
    for (int o = 0; o < 8; ++o) {
        n0 = fmaf(s[o], s[o], n0);
        n1 = fmaf(s[o + 8], s[o + 8], n1);
    }
    float n = n0 + n1;
    float f = sqrtf(n) / (1.f + n);
#pragma unroll
    for (int o = 0; o < COUT; ++o) v[o] = s[o] * f;
}

__device__ __forceinline__ float dot16(const float* a, const float* b) {
    float d0 = 0.f, d1 = 0.f, d2 = 0.f, d3 = 0.f;
#pragma unroll
    for (int o = 0; o < 4; ++o) {
        d0 = fmaf(a[o],      b[o],      d0);
        d1 = fmaf(a[o + 4],  b[o + 4],  d1);
        d2 = fmaf(a[o + 8],  b[o + 8],  d2);
        d3 = fmaf(a[o + 12], b[o + 12], d3);
    }
    return (d0 + d1) + (d2 + d3);
}

// one block = one (batch, k) pair; 2 CTAs per SM
__global__ __launch_bounds__(NTHREADS, 2)
void caps_kernel(const float* __restrict__ u) {
    extern __shared__ float sm[];
    uint4* tA = (uint4*)sm;            // outputs 0..7 of route r
    uint4* tB = tA + RR;               // outputs 8..15
    float* red0 = (float*)(tB + RR);   // ping-pong reduction buffers
    float* red1 = red0 + REDSZ;

    const int tid  = threadIdx.x;
    const int lane = tid & 31;
    const int wid  = tid >> 5;
    const int b    = blockIdx.x >> 1;
    const int k    = blockIdx.x & 1;
    const float4* up = (const float4*)(u + (size_t)b * RR * CIN);
    const bool tailok = (tid < TAILN);      // warp-uniform

    const uint4* Wk = g_Wh + k * (CIN * 2 * RR);

    // ===== Phase A: u_ji (half2) -> smem; init route-sum folded in =====
    half2 ssh[8];
#pragma unroll
    for (int p = 0; p < 8; ++p) ssh[p] = __floats2half2_rn(0.f, 0.f);

#define ROUTE_A(RVAL)                                                          \
    {                                                                          \
        const int r_ = (RVAL);                                                 \
        float4 a = up[r_];                                                     \
        half2 ah[4] = {__float2half2_rn(a.x), __float2half2_rn(a.y),           \
                       __float2half2_rn(a.z), __float2half2_rn(a.w)};          \
        half2 ac[8];                                                           \
        _Pragma("unroll")                                                      \
        for (int p = 0; p < 8; ++p) ac[p] = __floats2half2_rn(0.f, 0.f);       \
        _Pragma("unroll")                                                      \
        for (int i = 0; i < 4; ++i) {                                          \
            uint4 w0 = Wk[(i * 2 + 0) * RR + r_];                              \
            uint4 w1 = Wk[(i * 2 + 1) * RR + r_];                              \
            ac[0] = __hfma2(ah[i], H2(w0.x), ac[0]);                           \
            ac[1] = __hfma2(ah[i], H2(w0.y), ac[1]);                           \
            ac[2] = __hfma2(ah[i], H2(w0.z), ac[2]);                           \
            ac[3] = __hfma2(ah[i], H2(w0.w), ac[3]);                           \
            ac[4] = __hfma2(ah[i], H2(w1.x), ac[4]);                           \
            ac[5] = __hfma2(ah[i], H2(w1.y), ac[5]);                           \
            ac[6] = __hfma2(ah[i], H2(w1.z), ac[6]);                           \
            ac[7] = __hfma2(ah[i], H2(w1.w), ac[7]);                           \
        }                                                                      \
        uint4 sa, sb;                                                          \
        H2(sa.x) = ac[0]; H2(sa.y) = ac[1]; H2(sa.z) = ac[2]; H2(sa.w) = ac[3];\
        H2(sb.x) = ac[4]; H2(sb.y) = ac[5]; H2(sb.z) = ac[6]; H2(sb.w) = ac[7];\
        tA[r_] = sa; tB[r_] = sb;                                              \
        _Pragma("unroll")                                                      \
        for (int p = 0; p < 8; ++p) ssh[p] = __hadd2(ssh[p], ac[p]);           \
    }

#pragma unroll
    for (int j = 0; j < RPTF; ++j)
        ROUTE_A(tid + j * NTHREADS)
    if (tailok)
        ROUTE_A(tid + RPTF * NTHREADS)

    // ===== init reduction + squash (fp32) =====
    float v[COUT];
    {
        float ss[COUT];
#pragma unroll
        for (int p = 0; p < 8; ++p) {
            float2 f = __half22float2(ssh[p]);
            ss[2 * p] = f.x; ss[2 * p + 1] = f.y;
        }
        block_sum<COUT>(ss, red0, tid, lane, wid);
#pragma unroll
        for (int o = 0; o < COUT; ++o) ss[o] *= (1.f / RR);
        squash16(ss, v);
    }

    // ===== 2 fused routing iterations, half2 sweep math =====
    float blr[RPT];
#pragma unroll
    for (int it = 0; it < 2; ++it) {
        half2 vh[8];
#pragma unroll
        for (int p = 0; p < 8; ++p)
            vh[p] = __floats2half2_rn(v[2 * p], v[2 * p + 1]);
        half2 ach[8];
#pragma unroll
        for (int p = 0; p < 8; ++p) ach[p] = __floats2half2_rn(0.f, 0.f);
        float accw = 0.f;

#define SWEEP(JIDX, RVAL)                                                      \
        {                                                                      \
            const int r_ = (RVAL);                                             \
            uint4 qa = tA[r_], qb = tB[r_];                                    \
            half2 dp = __hmul2(H2(qa.x), vh[0]);                               \
            dp = __hfma2(H2(qa.y), vh[1], dp);                                 \
            dp = __hfma2(H2(qa.z), vh[2], dp);                                 \
            dp = __hfma2(H2(qa.w), vh[3], dp);                                 \
            dp = __hfma2(H2(qb.x), vh[4], dp);                                 \
            dp = __hfma2(H2(qb.y), vh[5], dp);                                 \
            dp = __hfma2(H2(qb.z), vh[6], dp);                                 \
            dp = __hfma2(H2(qb.w), vh[7], dp);                                 \
            float2 df = __half22float2(dp);                                    \
            float d = df.x + df.y;                                             \
            float nb = (it == 0) ? d : (blr[JIDX] + d);                        \
            blr[JIDX] = nb;                                                    \
            float w = __expf(nb);                                              \
            accw += w;                                                         \
            half2 wh = __float2half2_rn(w);                                    \
            ach[0] = __hfma2(wh, H2(qa.x), ach[0]);                            \
            ach[1] = __hfma2(wh, H2(qa.y), ach[1]);                            \
            ach[2] = __hfma2(wh, H2(qa.z), ach[2]);                            \
            ach[3] = __hfma2(wh, H2(qa.w), ach[3]);                            \
            ach[4] = __hfma2(wh, H2(qb.x), ach[4]);                            \
            ach[5] = __hfma2(wh, H2(qb.y), ach[5]);                            \
            ach[6] = __hfma2(wh, H2(qb.z), ach[6]);                            \
            ach[7] = __hfma2(wh, H2(qb.w), ach[7]);                            \
        }

#pragma unroll
        for (int j = 0; j < RPTF; ++j)
            SWEEP(j, tid + j * NTHREADS)
        if (tailok)
            SWEEP(RPT - 1, tid + RPTF * NTHREADS)

        float av[COUT + 1];
#pragma unroll
        for (int p = 0; p < 8; ++p) {
            float2 f = __half22float2(ach[p]);
            av[2 * p] = f.x; av[2 * p + 1] = f.y;
        }
        av[COUT] = accw;

        block_sum<COUT + 1>(av, (it == 0) ? red1 : red0, tid, lane, wid);

        float invZ = 1.f / av[COUT];
        float s[COUT];
#pragma unroll
        for (int o = 0; o < COUT; ++o) s[o] = av[o] * invZ;
        squash16(s, v);
    }

    if (tid == 0)
        g_cls[blockIdx.x] = sqrtf(dot16(v, v));   // blockIdx.x == b*2 + k
}

// epilogue: 2-way softmax per batch
__global__ void softmax_kernel(float* __restrict__ out) {
    int t = blockIdx.x * blockDim.x + threadIdx.x;
    if (t >= NB) return;
    float c0 = g_cls[2 * t + 0];
    float c1 = g_cls[2 * t + 1];
    float m = fmaxf(c0, c1);
    float e0 = __expf(c0 - m), e1 = __expf(c1 - m);
    float inv = 1.f / (e0 + e1);
    out[2 * t + 0] = e0 * inv;
    out[2 * t + 1] = e1 * inv;
}

extern "C" void kernel_launch(void* const* d_in, const int* in_sizes, int n_in,
                              void* d_out, int out_size) {
    const float* u = (const float*)d_in[0];   // [1024, 2336, 4]
    const float* W = (const float*)d_in[1];   // [2, 2336, 4, 16]
    float* out = (float*)d_out;               // [1024, 2]

    const int wtotal = NK * CIN * 2 * RR;
    wtrans_kernel<<<(wtotal + 255) / 256, 256>>>(W);

    const int smem_bytes = 2 * RR * sizeof(uint4) + 2 * REDSZ * sizeof(float);
    cudaFuncSetAttribute(caps_kernel,
                         cudaFuncAttributeMaxDynamicSharedMemorySize, smem_bytes);
    caps_kernel<<<NB * NK, NTHREADS, smem_bytes>>>(u);

    softmax_kernel<<<(NB + 255) / 256, 256>>>(out);
}